// round 8
// baseline (speedup 1.0000x reference)
#include <cuda_runtime.h>
#include <math.h>

#define BSZ   256
#define ISIZE 256
#define HSIZE 512
#define BH    (BSZ*HSIZE)
#define BK 16

#define NGATE  384            // 3 regions (x, hA, hB) x 4 gates x 32 tiles
#define NSLOTS 896            // + 512 reduce/update units (b, row-half)
#define GRID1  296            // 2 CTAs/SM x 148 SMs -> all co-resident

// Scratch (device globals)
__device__ __align__(16) float g_prex[4*BH];    // x-side gate partials
__device__ __align__(16) float g_preh0[4*BH];   // h-side partials, K rows 0..255
__device__ __align__(16) float g_preh1[4*BH];   // h-side partials, K rows 256..511
__device__ __align__(16) float g_hredp[2*BH];   // hred partials per row-half
__device__ int g_gatecnt;                       // completed gate units
__device__ int g_redcnt[BSZ];                   // completed row-halves per batch

// ---------------------------------------------------------------------------
// K0: zero the sync counters (scratch persists across graph replays)
// ---------------------------------------------------------------------------
__global__ void kzero()
{
    g_redcnt[threadIdx.x] = 0;
    if (threadIdx.x == 0) g_gatecnt = 0;
}

// ---------------------------------------------------------------------------
// KMAIN: persistent fused kernel. 296 CTAs x 512 threads, all resident.
// Slots [0,384):  gate GEMM units (64x64 tile, K=256 chunk).
// Slots [384,896): unit (b, rh): reduce rows [rh*256, rh*256+256) of hebb[b],
//   sync (gates done + both halves of b reduced), compute its/cell/hactiv/m/ei,
//   then IMMEDIATELY update the same rows (hebb reread is L2-hot).
// Sibling units (b,0),(b,1) land on adjacent CTAs in the same round.
// ---------------------------------------------------------------------------
__global__ __launch_bounds__(512, 2)
void kmain(const float* __restrict__ x, const float* __restrict__ h0,
           const float* __restrict__ hebb, const float* __restrict__ c0,
           const float* __restrict__ alpha,
           const float* __restrict__ x2f, const float* __restrict__ x2i,
           const float* __restrict__ x2o, const float* __restrict__ x2c,
           const float* __restrict__ h2f, const float* __restrict__ h2i,
           const float* __restrict__ h2o, const float* __restrict__ w,
           const float* __restrict__ x2f_b, const float* __restrict__ h2f_b,
           const float* __restrict__ x2i_b, const float* __restrict__ h2i_b,
           const float* __restrict__ x2o_b, const float* __restrict__ h2o_b,
           const float* __restrict__ x2c_b,
           const float* __restrict__ h2mod_w, const float* __restrict__ h2mod_b,
           const float* __restrict__ mfw, const float* __restrict__ mfb,
           float* __restrict__ out_hact, float* __restrict__ out_cell,
           float* __restrict__ out_hebb)
{
    __shared__ union {
        struct {                                   // reduce/update path
            float4 sp[512];                        // 8KB partials
            float  sh0[256];                       // h0 rows of this half
            float  sei[512];                       // ei row vector
            float  sred[16];
            float  smv;
        } r;
        struct { float As[BK][68]; float Ws[BK][68]; } t;   // gate path
    } sm;

    int tid = threadIdx.x;

    for (int s = blockIdx.x; s < NSLOTS; s += GRID1) {
        if (s >= NGATE) {
            // ============ reduce + update unit (b, rh) =====================
            int ru = s - NGATE;
            int b = ru >> 1;
            int rh = ru & 1;

            if (tid < 256) sm.r.sh0[tid] = h0[b * HSIZE + rh * 256 + tid];
            __syncthreads();

            int g = tid >> 7;                      // row-group 0..3 (64 rows)
            int c = tid & 127;                     // f4 column
            const float4* hb4 = (const float4*)(hebb + (size_t)b * HSIZE * HSIZE)
                                + (size_t)(rh * 256 + g * 64) * 128 + c;
            const float* s0 = &sm.r.sh0[g * 64];

            float4 acc = make_float4(0.f, 0.f, 0.f, 0.f);
#pragma unroll 8
            for (int i = 0; i < 64; ++i) {
                float sv = s0[i];
                float4 v = hb4[(size_t)i * 128];
                acc.x = fmaf(sv, v.x, acc.x);
                acc.y = fmaf(sv, v.y, acc.y);
                acc.z = fmaf(sv, v.z, acc.z);
                acc.w = fmaf(sv, v.w, acc.w);
            }
            sm.r.sp[tid] = acc;
            __syncthreads();
            if (g == 0) {
                float4 a = sm.r.sp[tid];
                float4 b2 = sm.r.sp[128 + tid];
                float4 d = sm.r.sp[256 + tid];
                float4 e = sm.r.sp[384 + tid];
                a.x += b2.x + d.x + e.x;
                a.y += b2.y + d.y + e.y;
                a.z += b2.z + d.z + e.z;
                a.w += b2.w + d.w + e.w;
                ((float4*)(g_hredp + (size_t)rh * BH + b * HSIZE))[tid] = a;
                __threadfence();
            }
            __syncthreads();
            if (tid == 0) {
                atomicAdd(&g_redcnt[b], 1);
                while (*(volatile int*)&g_gatecnt != NGATE) __nanosleep(64);
                while (*(volatile int*)&g_redcnt[b] != 2) __nanosleep(32);
                __threadfence();
            }
            __syncthreads();

            // ---- per-batch math: thread k = tid owns column k ------------
            int k = tid;
            int idx = b * HSIZE + k;
            float pf = g_prex[idx]          + g_preh0[idx]          + g_preh1[idx]
                     + x2f_b[k] + h2f_b[k];
            float pi = g_prex[BH + idx]     + g_preh0[BH + idx]     + g_preh1[BH + idx]
                     + x2i_b[k] + h2i_b[k];
            float po = g_prex[2 * BH + idx] + g_preh0[2 * BH + idx] + g_preh1[2 * BH + idx]
                     + x2o_b[k] + h2o_b[k];
            float hred = g_hredp[idx] + g_hredp[BH + idx];
            float pc = g_prex[3 * BH + idx] + g_preh0[3 * BH + idx] + g_preh1[3 * BH + idx]
                     + x2c_b[k] + alpha[k] * hred;
            float fgt = 1.f / (1.f + expf(-pf));
            float ipt = 1.f / (1.f + expf(-pi));
            float opt = 1.f / (1.f + expf(-po));
            float its = tanhf(pc);
            float cell = fgt * c0[idx] + ipt * its;
            float hact = opt * tanhf(cell);
            out_cell[idx] = cell;        // both halves write identical values
            out_hact[idx] = hact;

            float mv = hact * h2mod_w[k];
#pragma unroll
            for (int o = 16; o > 0; o >>= 1)
                mv += __shfl_down_sync(0xffffffffu, mv, o);
            if ((k & 31) == 0) sm.r.sred[k >> 5] = mv;
            __syncthreads();
            if (k == 0) {
                float t2 = 0.f;
#pragma unroll
                for (int i = 0; i < 16; i++) t2 += sm.r.sred[i];
                sm.r.smv = tanhf(t2 + h2mod_b[0]);
            }
            __syncthreads();
            sm.r.sei[k] = fmaf(sm.r.smv, mfw[k], mfb[k]) * its;
            __syncthreads();

            // ---- update own rows (reverse order -> L2-hot reread) --------
            float4 e4 = ((const float4*)sm.r.sei)[c];
            float4* ob4 = (float4*)(out_hebb + (size_t)b * HSIZE * HSIZE)
                          + (size_t)(rh * 256 + g * 64) * 128 + c;
#pragma unroll 4
            for (int i = 63; i >= 0; --i) {
                float sv = s0[i];
                float4 v = hb4[(size_t)i * 128];
                float4 o;
                float t;
                t = fmaf(sv, e4.x, v.x); o.x = fminf(fmaxf(t, -2.f), 2.f);
                t = fmaf(sv, e4.y, v.y); o.y = fminf(fmaxf(t, -2.f), 2.f);
                t = fmaf(sv, e4.z, v.z); o.z = fminf(fmaxf(t, -2.f), 2.f);
                t = fmaf(sv, e4.w, v.w); o.w = fminf(fmaxf(t, -2.f), 2.f);
                ob4[(size_t)i * 128] = o;
            }
            __syncthreads();
        } else {
            // ============ gate GEMM unit (16 k-tiles) ======================
            int region = s >> 7;           // 0=x, 1=h rows 0..255, 2=h rows 256..511
            int r = s & 127;
            int gate = r >> 5;
            int ct = r & 31;
            int bn0 = (ct & 7) * 64;
            int bm0 = (ct >> 3) * 64;
            const float* A = region ? h0 : x;
            int KA = region ? HSIZE : ISIZE;
            int kbeg = (region == 2) ? 256 : 0;
            const float* W;
            if (region == 0)
                W = (gate == 0) ? x2f : (gate == 1) ? x2i : (gate == 2) ? x2o : x2c;
            else
                W = (gate == 0) ? h2f : (gate == 1) ? h2i : (gate == 2) ? h2o : w;
            bool trans = (region >= 1) && (gate == 3);   // w is [h,k]

            int tx = tid & 15, ty = tid >> 4;
            float acc[2][4] = {};

            for (int kt = 0; kt < 16; ++kt) {
                int k0 = kbeg + kt * BK;
#pragma unroll
                for (int l = 0; l < 2; l++) {
                    int e = tid + l * 512; int rr = e >> 4; int cc = e & 15;
                    sm.t.As[cc][rr] = A[(size_t)(bm0 + rr) * KA + k0 + cc];
                }
                if (trans) {
#pragma unroll
                    for (int l = 0; l < 2; l++) {
                        int e = tid + l * 512; int rr = e & 63; int cc = e >> 6;
                        sm.t.Ws[cc][rr] = W[(size_t)(k0 + cc) * HSIZE + bn0 + rr];
                    }
                } else {
#pragma unroll
                    for (int l = 0; l < 2; l++) {
                        int e = tid + l * 512; int rr = e >> 4; int cc = e & 15;
                        sm.t.Ws[cc][rr] = W[(size_t)(bn0 + rr) * KA + k0 + cc];
                    }
                }
                __syncthreads();
#pragma unroll
                for (int kb = 0; kb < BK; kb++) {
                    float2 ra = *(const float2*)&sm.t.As[kb][ty * 2];
                    float4 rb = *(const float4*)&sm.t.Ws[kb][tx * 4];
                    float a[2] = {ra.x, ra.y};
                    float bv[4] = {rb.x, rb.y, rb.z, rb.w};
#pragma unroll
                    for (int i = 0; i < 2; i++)
#pragma unroll
                        for (int j = 0; j < 4; j++)
                            acc[i][j] = fmaf(a[i], bv[j], acc[i][j]);
                }
                __syncthreads();
            }
            float* outb = (region == 0 ? g_prex : region == 1 ? g_preh0 : g_preh1)
                        + (size_t)gate * BH;
#pragma unroll
            for (int i = 0; i < 2; i++) {
                int bb = bm0 + ty * 2 + i;
#pragma unroll
                for (int j = 0; j < 4; j++)
                    outb[(size_t)bb * HSIZE + bn0 + tx * 4 + j] = acc[i][j];
            }
            __threadfence();
            __syncthreads();
            if (tid == 0) atomicAdd(&g_gatecnt, 1);
            __syncthreads();
        }
    }
}

// ---------------------------------------------------------------------------
extern "C" void kernel_launch(void* const* d_in, const int* in_sizes, int n_in,
                              void* d_out, int out_size)
{
    const float* inputs  = (const float*)d_in[0];
    const float* h0      = (const float*)d_in[1];
    const float* c0      = (const float*)d_in[2];
    const float* hebb    = (const float*)d_in[3];
    const float* w       = (const float*)d_in[4];
    const float* alpha   = (const float*)d_in[5];
    const float* h2f_w   = (const float*)d_in[6];
    const float* h2f_b   = (const float*)d_in[7];
    const float* h2i_w   = (const float*)d_in[8];
    const float* h2i_b   = (const float*)d_in[9];
    const float* h2o_w   = (const float*)d_in[10];
    const float* h2o_b   = (const float*)d_in[11];
    const float* x2f_w   = (const float*)d_in[12];
    const float* x2f_b   = (const float*)d_in[13];
    const float* x2i_w   = (const float*)d_in[14];
    const float* x2i_b   = (const float*)d_in[15];
    const float* x2o_w   = (const float*)d_in[16];
    const float* x2o_b   = (const float*)d_in[17];
    const float* x2c_w   = (const float*)d_in[18];
    const float* x2c_b   = (const float*)d_in[19];
    const float* h2mod_w = (const float*)d_in[20];
    const float* h2mod_b = (const float*)d_in[21];
    const float* mfw     = (const float*)d_in[22];
    const float* mfb     = (const float*)d_in[23];

    float* out       = (float*)d_out;
    float* out_hact  = out;              // [B,H]
    float* out_cell  = out + BH;         // [B,H]
    float* out_hebb  = out + 2 * BH;     // [B,H,H]

    kzero<<<1, 256>>>();

    kmain<<<GRID1, 512>>>(inputs, h0, hebb, c0, alpha,
                          x2f_w, x2i_w, x2o_w, x2c_w,
                          h2f_w, h2i_w, h2o_w, w,
                          x2f_b, h2f_b, x2i_b, h2i_b, x2o_b, h2o_b, x2c_b,
                          h2mod_w, h2mod_b, mfw, mfb,
                          out_hact, out_cell, out_hebb);
}